// round 1
// baseline (speedup 1.0000x reference)
#include <cuda_runtime.h>

#define BATCH 512
#define NN    4096
#define KK    256
#define EPSF  0.1f
#define ITERS 200
#define PADF  1e-16f

#define TPB   512          // threads per sinkhorn block
#define EPT   (NN / TPB)   // 8 elements per thread

__device__ unsigned int g_cmax_bits;

__global__ void init_kernel() {
    g_cmax_bits = 0u;
}

// Global max of C = max over all elements of max(s^2, (s-1)^2). All values >= 0,
// so uint bit-compare == float compare.
__global__ void max_kernel(const float* __restrict__ scores) {
    float m = 0.0f;
    int total = BATCH * NN;
    for (int i = blockIdx.x * blockDim.x + threadIdx.x; i < total;
         i += gridDim.x * blockDim.x) {
        float s  = scores[i];
        float c0 = s * s;
        float s1 = s - 1.0f;
        float c1 = s1 * s1;
        m = fmaxf(m, fmaxf(c0, c1));
    }
#pragma unroll
    for (int o = 16; o > 0; o >>= 1)
        m = fmaxf(m, __shfl_xor_sync(0xFFFFFFFFu, m, o));
    if ((threadIdx.x & 31) == 0)
        atomicMax(&g_cmax_bits, __float_as_uint(m));
}

// One block per batch row. G0, G1, v register-resident (8 elems/thread).
__global__ void __launch_bounds__(TPB, 2)
sinkhorn_kernel(const float* __restrict__ scores, float* __restrict__ out) {
    const int b = blockIdx.x;
    const int t = threadIdx.x;

    const float cmax = __uint_as_float(g_cmax_bits);
    const float inv  = __fdividef(1.0f, cmax * EPSF);   // exp(-C/(cmax*eps))

    float G0[EPT], G1[EPT], v[EPT];
#pragma unroll
    for (int i = 0; i < EPT; i++) {
        float s  = scores[b * NN + t + i * TPB];
        float s1 = s - 1.0f;
        G0[i] = __expf(-s * s * inv);
        G1[i] = __expf(-s1 * s1 * inv);
        v[i]  = 1.0f;
    }

    __shared__ float red0[16];
    __shared__ float red1[16];
    __shared__ float ubc[2];

    const float nu0 = (float)KK / (float)NN;
    const float nu1 = (float)(NN - KK) / (float)NN;
    const float mu  = 1.0f / (float)NN;

    float u0 = 0.0f, u1 = 0.0f;

    for (int it = 0; it < ITERS; it++) {
        // partial dot products G0.v and G1.v
        float s0 = 0.0f, s1 = 0.0f;
#pragma unroll
        for (int i = 0; i < EPT; i++) {
            s0 = fmaf(G0[i], v[i], s0);
            s1 = fmaf(G1[i], v[i], s1);
        }
        // warp reduce
#pragma unroll
        for (int o = 16; o > 0; o >>= 1) {
            s0 += __shfl_xor_sync(0xFFFFFFFFu, s0, o);
            s1 += __shfl_xor_sync(0xFFFFFFFFu, s1, o);
        }
        const int w = t >> 5;
        if ((t & 31) == 0) { red0[w] = s0; red1[w] = s1; }
        __syncthreads();
        // warp 0: lanes 0-15 reduce red0, lanes 16-31 reduce red1
        if (t < 32) {
            float a = (t < 16) ? red0[t] : red1[t - 16];
            a += __shfl_xor_sync(0xFFFFFFFFu, a, 8);
            a += __shfl_xor_sync(0xFFFFFFFFu, a, 4);
            a += __shfl_xor_sync(0xFFFFFFFFu, a, 2);
            a += __shfl_xor_sync(0xFFFFFFFFu, a, 1);
            if ((t & 15) == 0) ubc[t >> 4] = a;
        }
        __syncthreads();

        u0 = __fdividef(nu0, ubc[0] + PADF);
        u1 = __fdividef(nu1, ubc[1] + PADF);

        // v_n = mu / (u0*G0 + u1*G1 + PAD)
#pragma unroll
        for (int i = 0; i < EPT; i++) {
            float d = fmaf(G0[i], u0, fmaf(G1[i], u1, PADF));
            v[i] = __fdividef(mu, d);
        }
    }

    // P[b,k,n] = u_k * G_k[n] * v[n]
    float* o0 = out + (size_t)b * 2 * NN;
    float* o1 = o0 + NN;
#pragma unroll
    for (int i = 0; i < EPT; i++) {
        int n = t + i * TPB;
        o0[n] = u0 * G0[i] * v[i];
        o1[n] = u1 * G1[i] * v[i];
    }
}

extern "C" void kernel_launch(void* const* d_in, const int* in_sizes, int n_in,
                              void* d_out, int out_size) {
    const float* scores = (const float*)d_in[0];
    float* out = (float*)d_out;

    init_kernel<<<1, 1>>>();
    max_kernel<<<592, 256>>>(scores);
    sinkhorn_kernel<<<BATCH, TPB>>>(scores, out);
}

// round 2
// speedup vs baseline: 3.5265x; 3.5265x over previous
#include <cuda_runtime.h>

#define BATCH 512
#define NN    4096
#define KK    256
#define EPSF  0.1f
#define ITERS 200
#define RHO   15.0f        // (N-K)/K
#define MUF   (1.0f / 4096.0f)

#define TPB   256
#define EPT   16           // elements per thread
#define NG    4            // quad-groups per thread

__device__ float g_pmax[BATCH];

__device__ __forceinline__ float frcp(float x) {
    float y;
    asm("rcp.approx.ftz.f32 %0, %1;" : "=f"(y) : "f"(x));
    return y;
}

// Per-row max of C = max(s^2, (s-1)^2). One block per row, plain store (no atomics/init).
__global__ void __launch_bounds__(TPB)
max_kernel(const float* __restrict__ scores) {
    const int b = blockIdx.x;
    const int t = threadIdx.x;
    float m = 0.0f;
#pragma unroll
    for (int i = 0; i < EPT; i++) {
        float s  = scores[b * NN + t + i * TPB];
        float s1 = s - 1.0f;
        m = fmaxf(m, fmaxf(s * s, s1 * s1));
    }
#pragma unroll
    for (int o = 16; o > 0; o >>= 1)
        m = fmaxf(m, __shfl_xor_sync(0xFFFFFFFFu, m, o));
    __shared__ float red[8];
    if ((t & 31) == 0) red[t >> 5] = m;
    __syncthreads();
    if (t < 32) {
        float x = red[t & 7];
        x = fmaxf(x, __shfl_xor_sync(0xFFFFFFFFu, x, 4));
        x = fmaxf(x, __shfl_xor_sync(0xFFFFFFFFu, x, 2));
        x = fmaxf(x, __shfl_xor_sync(0xFFFFFFFFu, x, 1));
        if (t == 0) g_pmax[b] = x;
    }
}

// One block per row. Collapsed scalar Sinkhorn: w = u1/u0,
// T(w) = sum_n 1/(1 + w r_n),  w <- RHO * w * T/(N-T).
__global__ void __launch_bounds__(TPB, 4)
sinkhorn_kernel(const float* __restrict__ scores, float* __restrict__ out) {
    const int b = blockIdx.x;
    const int t = threadIdx.x;
    const int w5 = t >> 5;      // warp id
    const int lane = t & 31;

    __shared__ float pre[24];        // [0:8) cmax, [8:16) sum0, [16:24) sum1
    __shared__ float red[2][8];      // double-buffered T partials

    // ---- global cmax from per-row partials (L2-hot) ----
    float m = fmaxf(g_pmax[t], g_pmax[t + 256]);
#pragma unroll
    for (int o = 16; o > 0; o >>= 1)
        m = fmaxf(m, __shfl_xor_sync(0xFFFFFFFFu, m, o));
    if (lane == 0) pre[w5] = m;
    __syncthreads();
    {
        float x = pre[t & 7];
        x = fmaxf(x, __shfl_xor_sync(0xFFFFFFFFu, x, 4));
        x = fmaxf(x, __shfl_xor_sync(0xFFFFFFFFu, x, 2));
        x = fmaxf(x, __shfl_xor_sync(0xFFFFFFFFu, x, 1));
        m = x;
    }
    const float inv = frcp(m * EPSF);   // 1/(cmax*eps)

    // ---- prologue: r_n = exp((2s-1)*inv), sums of G0,G1, symmetric funcs ----
    float e1[NG], e2[NG], e3[NG], e4[NG];
    float sum0 = 0.0f, sum1 = 0.0f;
#pragma unroll
    for (int g = 0; g < NG; g++) {
        float r[4];
#pragma unroll
        for (int j = 0; j < 4; j++) {
            float s  = scores[b * NN + t + (g * 4 + j) * TPB];
            float g0 = __expf(-s * s * inv);
            r[j] = __expf((2.0f * s - 1.0f) * inv);
            sum0 += g0;
            sum1 = fmaf(g0, r[j], sum1);
        }
        float s12 = r[0] + r[1], p12 = r[0] * r[1];
        float s34 = r[2] + r[3], p34 = r[2] * r[3];
        e1[g] = s12 + s34;
        e2[g] = fmaf(s12, s34, p12 + p34);
        e3[g] = fmaf(p12, s34, p34 * s12);
        e4[g] = p12 * p34;
    }

    // block-reduce sum0, sum1
#pragma unroll
    for (int o = 16; o > 0; o >>= 1) {
        sum0 += __shfl_xor_sync(0xFFFFFFFFu, sum0, o);
        sum1 += __shfl_xor_sync(0xFFFFFFFFu, sum1, o);
    }
    __syncthreads();   // pre[0:8) reads done before rewrite
    if (lane == 0) { pre[8 + w5] = sum0; pre[16 + w5] = sum1; }
    __syncthreads();
    {
        float a = pre[8 + (t & 7)];
        float c = pre[16 + (t & 7)];
#pragma unroll
        for (int o = 4; o > 0; o >>= 1) {
            a += __shfl_xor_sync(0xFFFFFFFFu, a, o);
            c += __shfl_xor_sync(0xFFFFFFFFu, c, o);
        }
        sum0 = a; sum1 = c;
    }

    float w = RHO * sum0 * frcp(sum1);   // w after first u-update (v = 1)

    // ---- 199 scalar iterations ----
    int par = 0;
    for (int it = 1; it < ITERS; it++) {
        float w2 = w * w;
        float w3 = w2 * w;
        float w4 = w2 * w2;
        float b1 = 3.0f * w;
        float b2 = 2.0f * w2;
        float T = 0.0f;
#pragma unroll
        for (int g = 0; g < NG; g++) {
            float p = fmaf(e4[g], w4, fmaf(e3[g], w3, fmaf(e2[g], w2, fmaf(e1[g], w, 1.0f))));
            float n = fmaf(e3[g], w3, fmaf(e2[g], b2, fmaf(e1[g], b1, 4.0f)));
            T = fmaf(n, frcp(p), T);
        }
#pragma unroll
        for (int o = 16; o > 0; o >>= 1)
            T += __shfl_xor_sync(0xFFFFFFFFu, T, o);
        if (lane == 0) red[par][w5] = T;
        __syncthreads();
        {
            float x = red[par][t & 7];
            x += __shfl_xor_sync(0xFFFFFFFFu, x, 4);
            x += __shfl_xor_sync(0xFFFFFFFFu, x, 2);
            x += __shfl_xor_sync(0xFFFFFFFFu, x, 1);
            T = x;
        }
        float wn = RHO * w * T * frcp((float)NN - T);
        float dw = fabsf(wn - w);
        w = wn;
        par ^= 1;
        if (dw <= 3e-8f * wn) break;   // trajectory static in fp32; uniform across block
    }

    // ---- epilogue: P0 = mu/(1+w r), P1 = mu - P0 ----
    float* o0 = out + (size_t)b * 2 * NN;
    float* o1 = o0 + NN;
#pragma unroll
    for (int i = 0; i < EPT; i++) {
        int n = t + i * TPB;
        float s = scores[b * NN + n];
        float r = __expf((2.0f * s - 1.0f) * inv);
        float P0 = MUF * frcp(fmaf(w, r, 1.0f));
        o0[n] = P0;
        o1[n] = MUF - P0;
    }
}

extern "C" void kernel_launch(void* const* d_in, const int* in_sizes, int n_in,
                              void* d_out, int out_size) {
    const float* scores = (const float*)d_in[0];
    float* out = (float*)d_out;

    max_kernel<<<BATCH, TPB>>>(scores);
    sinkhorn_kernel<<<BATCH, TPB>>>(scores, out);
}

// round 3
// speedup vs baseline: 18.8004x; 5.3312x over previous
#include <cuda_runtime.h>

#define BATCH 512
#define NN    4096
#define KK    256
#define EPSF  0.1f
#define RHO   15.0f              // (N-K)/K
#define MUF   (1.0f / 4096.0f)
#define KF    256.0f

#define TPB   256
#define NG    4                  // float4 quad-groups per thread (16 elems)

__device__ float g_pmax[BATCH];

__device__ __forceinline__ float frcp(float x) {
    float y;
    asm("rcp.approx.ftz.f32 %0, %1;" : "=f"(y) : "f"(x));
    return y;
}

// Per-row max of C = max(s^2, (s-1)^2), float4 loads.
__global__ void __launch_bounds__(TPB)
max_kernel(const float* __restrict__ scores) {
    const int b = blockIdx.x;
    const int t = threadIdx.x;
    const float4* s4 = (const float4*)(scores + b * NN);
    float m = 0.0f;
#pragma unroll
    for (int g = 0; g < NG; g++) {
        float4 s = s4[g * TPB + t];
        float a0 = s.x - 1.0f, a1 = s.y - 1.0f, a2 = s.z - 1.0f, a3 = s.w - 1.0f;
        m = fmaxf(m, fmaxf(fmaxf(s.x * s.x, a0 * a0), fmaxf(s.y * s.y, a1 * a1)));
        m = fmaxf(m, fmaxf(fmaxf(s.z * s.z, a2 * a2), fmaxf(s.w * s.w, a3 * a3)));
    }
#pragma unroll
    for (int o = 16; o > 0; o >>= 1)
        m = fmaxf(m, __shfl_xor_sync(0xFFFFFFFFu, m, o));
    __shared__ float red[8];
    if ((t & 31) == 0) red[t >> 5] = m;
    __syncthreads();
    if (t < 32) {
        float x = red[t & 7];
        x = fmaxf(x, __shfl_xor_sync(0xFFFFFFFFu, x, 4));
        x = fmaxf(x, __shfl_xor_sync(0xFFFFFFFFu, x, 2));
        x = fmaxf(x, __shfl_xor_sync(0xFFFFFFFFu, x, 1));
        if (t == 0) g_pmax[b] = x;
    }
}

// One block per row. Solve T(w) = sum_n 1/(1 + w r_n) = K by log-domain Newton.
// r_n = exp((2 s_n - 1) / (cmax * eps)). Quad groups give 1 RCP per 4 elems.
__global__ void __launch_bounds__(TPB, 4)
sinkhorn_kernel(const float* __restrict__ scores, float* __restrict__ out) {
    const int b = blockIdx.x;
    const int t = threadIdx.x;
    const int wrp = t >> 5;
    const int lane = t & 31;

    __shared__ float pre[8];
    __shared__ float red[2][2][8];   // [parity][T/Td][warp]

    // ---- global cmax from per-row partials ----
    float m = fmaxf(g_pmax[t], g_pmax[t + 256]);
#pragma unroll
    for (int o = 16; o > 0; o >>= 1)
        m = fmaxf(m, __shfl_xor_sync(0xFFFFFFFFu, m, o));
    if (lane == 0) pre[wrp] = m;
    __syncthreads();
    {
        float x = pre[t & 7];
        x = fmaxf(x, __shfl_xor_sync(0xFFFFFFFFu, x, 4));
        x = fmaxf(x, __shfl_xor_sync(0xFFFFFFFFu, x, 2));
        x = fmaxf(x, __shfl_xor_sync(0xFFFFFFFFu, x, 1));
        m = x;
    }
    const float inv = frcp(m * EPSF);

    // ---- prologue: r per quad -> elementary symmetric funcs; sum of r ----
    const float4* s4 = (const float4*)(scores + b * NN);
    float e1[NG], e2[NG], e3[NG], e4[NG];
    float sumr = 0.0f;
#pragma unroll
    for (int g = 0; g < NG; g++) {
        float4 s = s4[g * TPB + t];
        float r0 = __expf(fmaf(2.0f, s.x, -1.0f) * inv);
        float r1 = __expf(fmaf(2.0f, s.y, -1.0f) * inv);
        float r2 = __expf(fmaf(2.0f, s.z, -1.0f) * inv);
        float r3 = __expf(fmaf(2.0f, s.w, -1.0f) * inv);
        float s12 = r0 + r1, p12 = r0 * r1;
        float s34 = r2 + r3, p34 = r2 * r3;
        e1[g] = s12 + s34;
        e2[g] = fmaf(s12, s34, p12 + p34);
        e3[g] = fmaf(p12, s34, p34 * s12);
        e4[g] = p12 * p34;
        sumr += e1[g];
    }
#pragma unroll
    for (int o = 16; o > 0; o >>= 1)
        sumr += __shfl_xor_sync(0xFFFFFFFFu, sumr, o);
    if (lane == 0) red[0][0][wrp] = sumr;
    __syncthreads();
    {
        float x = red[0][0][t & 7];
        x += __shfl_xor_sync(0xFFFFFFFFu, x, 4);
        x += __shfl_xor_sync(0xFFFFFFFFu, x, 2);
        x += __shfl_xor_sync(0xFFFFFFFFu, x, 1);
        sumr = x;
    }

    // mean-field initial guess: T(w) ~ N/(1 + w*mean(r)) = K  ->  w = RHO*N/sum(r)
    float w = RHO * (float)NN * frcp(sumr);

    // ---- log-domain Newton on f(w) = T(w) - K ----
    int par = 1;
    for (int it = 0; it < 20; it++) {
        float T = 0.0f, Td = 0.0f;
#pragma unroll
        for (int g = 0; g < NG; g++) {
            // p  = 1 + e1 w + e2 w^2 + e3 w^3 + e4 w^4
            // n  = sum prod_{j!=i}(1+w r_j) = 4 + 3e1 w + 2e2 w^2 + e3 w^3
            // p' = e1 + 2e2 w + 3e3 w^2 + 4e4 w^3
            // n' = 3e1 + 4e2 w + 3e3 w^2
            float p  = fmaf(fmaf(fmaf(fmaf(e4[g], w, e3[g]), w, e2[g]), w, e1[g]), w, 1.0f);
            float n  = fmaf(fmaf(fmaf(e3[g], w, 2.0f * e2[g]), w, 3.0f * e1[g]), w, 4.0f);
            float pp = fmaf(fmaf(fmaf(4.0f * e4[g], w, 3.0f * e3[g]), w, 2.0f * e2[g]), w, e1[g]);
            float np = fmaf(fmaf(3.0f * e3[g], w, 4.0f * e2[g]), w, 3.0f * e1[g]);
            float rp = frcp(p);
            float tg = n * rp;
            T += tg;
            Td = fmaf(rp, fmaf(-tg, pp, np), Td);   // (n' - T_g p')/p
        }
#pragma unroll
        for (int o = 16; o > 0; o >>= 1) {
            T  += __shfl_xor_sync(0xFFFFFFFFu, T, o);
            Td += __shfl_xor_sync(0xFFFFFFFFu, Td, o);
        }
        if (lane == 0) { red[par][0][wrp] = T; red[par][1][wrp] = Td; }
        __syncthreads();
        {
            float x = red[par][0][t & 7];
            float y = red[par][1][t & 7];
#pragma unroll
            for (int o = 4; o > 0; o >>= 1) {
                x += __shfl_xor_sync(0xFFFFFFFFu, x, o);
                y += __shfl_xor_sync(0xFFFFFFFFu, y, o);
            }
            T = x; Td = y;
        }
        float f = T - KF;
        // Newton in x = ln w:  dT/dx = w*Td;  step = f/(w*Td)  (Td < 0)
        float step = f * frcp(w * Td);
        step = fminf(4.0f, fmaxf(-4.0f, step));
        w = w * __expf(-step);
        par ^= 1;
        if (fabsf(f) <= 2e-3f) break;   // |T-K| tolerance; uniform across block
    }

    // ---- epilogue: P0 = mu/(1+w r), P1 = mu - P0 ----
    float4* o0 = (float4*)(out + (size_t)b * 2 * NN);
    float4* o1 = (float4*)(out + (size_t)b * 2 * NN + NN);
#pragma unroll
    for (int g = 0; g < NG; g++) {
        float4 s = s4[g * TPB + t];
        float4 P0, P1;
        P0.x = MUF * frcp(fmaf(w, __expf(fmaf(2.0f, s.x, -1.0f) * inv), 1.0f));
        P0.y = MUF * frcp(fmaf(w, __expf(fmaf(2.0f, s.y, -1.0f) * inv), 1.0f));
        P0.z = MUF * frcp(fmaf(w, __expf(fmaf(2.0f, s.z, -1.0f) * inv), 1.0f));
        P0.w = MUF * frcp(fmaf(w, __expf(fmaf(2.0f, s.w, -1.0f) * inv), 1.0f));
        P1.x = MUF - P0.x;
        P1.y = MUF - P0.y;
        P1.z = MUF - P0.z;
        P1.w = MUF - P0.w;
        o0[g * TPB + t] = P0;
        o1[g * TPB + t] = P1;
    }
}

extern "C" void kernel_launch(void* const* d_in, const int* in_sizes, int n_in,
                              void* d_out, int out_size) {
    const float* scores = (const float*)d_in[0];
    float* out = (float*)d_out;

    max_kernel<<<BATCH, TPB>>>(scores);
    sinkhorn_kernel<<<BATCH, TPB>>>(scores, out);
}

// round 4
// speedup vs baseline: 19.1253x; 1.0173x over previous
#include <cuda_runtime.h>

#define BATCH 512
#define NN    4096
#define KK    256
#define EPSF  0.1f
#define MUF   (1.0f / 4096.0f)
#define KF    256.0f
#define L2E   1.4426950408889634f
#define LN2   0.6931471805599453f

#define TPB   256
#define NG    4                  // float4 quad-groups per thread (16 elems)

__device__ float g_pmax[BATCH];

__device__ __forceinline__ float frcp(float x) {
    float y; asm("rcp.approx.ftz.f32 %0, %1;" : "=f"(y) : "f"(x)); return y;
}
__device__ __forceinline__ float fex2(float x) {
    float y; asm("ex2.approx.ftz.f32 %0, %1;" : "=f"(y) : "f"(x)); return y;
}
__device__ __forceinline__ float flg2(float x) {
    float y; asm("lg2.approx.ftz.f32 %0, %1;" : "=f"(y) : "f"(x)); return y;
}

// Per-row max of C = max(s^2, (s-1)^2), float4 loads.
__global__ void __launch_bounds__(TPB)
max_kernel(const float* __restrict__ scores) {
    const int b = blockIdx.x;
    const int t = threadIdx.x;
    const float4* s4 = (const float4*)(scores + b * NN);
    float m = 0.0f;
#pragma unroll
    for (int g = 0; g < NG; g++) {
        float4 s = s4[g * TPB + t];
        float a0 = s.x - 1.0f, a1 = s.y - 1.0f, a2 = s.z - 1.0f, a3 = s.w - 1.0f;
        m = fmaxf(m, fmaxf(fmaxf(s.x * s.x, a0 * a0), fmaxf(s.y * s.y, a1 * a1)));
        m = fmaxf(m, fmaxf(fmaxf(s.z * s.z, a2 * a2), fmaxf(s.w * s.w, a3 * a3)));
    }
#pragma unroll
    for (int o = 16; o > 0; o >>= 1)
        m = fmaxf(m, __shfl_xor_sync(0xFFFFFFFFu, m, o));
    __shared__ float red[8];
    if ((t & 31) == 0) red[t >> 5] = m;
    __syncthreads();
    if (t < 32) {
        float x = red[t & 7];
        x = fmaxf(x, __shfl_xor_sync(0xFFFFFFFFu, x, 4));
        x = fmaxf(x, __shfl_xor_sync(0xFFFFFFFFu, x, 2));
        x = fmaxf(x, __shfl_xor_sync(0xFFFFFFFFu, x, 1));
        if (t == 0) g_pmax[b] = x;
    }
}

// One block per row. Solve T(w) = sum_n 1/(1 + w r_n) = K, r_n = exp((2s-1)/(cmax*eps)).
// Moment-matched lognormal initial guess, then log-domain Newton (exact derivative).
// Grouped reciprocals: one RCP per 4 elements via product trick.
__global__ void __launch_bounds__(TPB, 4)
sinkhorn_kernel(const float* __restrict__ scores, float* __restrict__ out) {
    const int b = blockIdx.x;
    const int t = threadIdx.x;
    const int wrp = t >> 5;
    const int lane = t & 31;

    __shared__ float pre[24];        // [0:8) cmax, [8:16) sumr, [16:24) sumr2
    __shared__ float red[2][2][8];   // [parity][T/S2][warp]

    // ---- global cmax from per-row partials ----
    float m = fmaxf(g_pmax[t], g_pmax[t + 256]);
#pragma unroll
    for (int o = 16; o > 0; o >>= 1)
        m = fmaxf(m, __shfl_xor_sync(0xFFFFFFFFu, m, o));
    if (lane == 0) pre[wrp] = m;
    __syncthreads();
    {
        float x = pre[t & 7];
        x = fmaxf(x, __shfl_xor_sync(0xFFFFFFFFu, x, 4));
        x = fmaxf(x, __shfl_xor_sync(0xFFFFFFFFu, x, 2));
        x = fmaxf(x, __shfl_xor_sync(0xFFFFFFFFu, x, 1));
        m = x;
    }
    const float inv = frcp(m * EPSF);          // 1/(cmax*eps)
    const float ca = 2.0f * inv * L2E;         // r = ex2(ca*s + cb)
    const float cb = -inv * L2E;

    // ---- prologue: r in registers; first two moments ----
    const float4* s4 = (const float4*)(scores + b * NN);
    float r[4 * NG];
    float sumr = 0.0f, sumr2 = 0.0f;
#pragma unroll
    for (int g = 0; g < NG; g++) {
        float4 s = s4[g * TPB + t];
        float r0 = fex2(fmaf(ca, s.x, cb));
        float r1 = fex2(fmaf(ca, s.y, cb));
        float r2 = fex2(fmaf(ca, s.z, cb));
        float r3 = fex2(fmaf(ca, s.w, cb));
        r[4 * g + 0] = r0; r[4 * g + 1] = r1; r[4 * g + 2] = r2; r[4 * g + 3] = r3;
        sumr += (r0 + r1) + (r2 + r3);
        sumr2 = fmaf(r0, r0, fmaf(r1, r1, fmaf(r2, r2, fmaf(r3, r3, sumr2))));
    }
#pragma unroll
    for (int o = 16; o > 0; o >>= 1) {
        sumr  += __shfl_xor_sync(0xFFFFFFFFu, sumr, o);
        sumr2 += __shfl_xor_sync(0xFFFFFFFFu, sumr2, o);
    }
    __syncthreads();   // pre[0:8) reads complete before rewrite
    if (lane == 0) { pre[8 + wrp] = sumr; pre[16 + wrp] = sumr2; }
    __syncthreads();
    {
        float a = pre[8 + (t & 7)];
        float c = pre[16 + (t & 7)];
#pragma unroll
        for (int o = 4; o > 0; o >>= 1) {
            a += __shfl_xor_sync(0xFFFFFFFFu, a, o);
            c += __shfl_xor_sync(0xFFFFFFFFu, c, o);
        }
        sumr = a; sumr2 = c;
    }

    // ---- moment-matched lognormal guess: w0 = exp(-(mu + z*sigma)) ----
    // m1 = E[r], m2 = E[r^2]; sig2 = ln(m2/m1^2); mu = ln(m1) - sig2/2
    const float m1l = flg2(sumr * MUF);                 // log2 m1
    const float m2l = flg2(sumr2 * MUF);                // log2 m2
    float sig2 = fmaxf(0.0f, (m2l - 2.0f * m1l) * LN2);
    float mu_l = m1l * LN2 - 0.5f * sig2;
    float w = fex2((-mu_l - 1.53412f * sqrtf(sig2)) * L2E);

    // ---- log-domain Newton: dT/dlnw = -(T - S2), S2 = sum inv^2 ----
    int par = 0;
    for (int it = 0; it < 10; it++) {
        float T = 0.0f, S2 = 0.0f;
#pragma unroll
        for (int g = 0; g < NG; g++) {
            float d0 = fmaf(w, r[4 * g + 0], 1.0f);
            float d1 = fmaf(w, r[4 * g + 1], 1.0f);
            float d2 = fmaf(w, r[4 * g + 2], 1.0f);
            float d3 = fmaf(w, r[4 * g + 3], 1.0f);
            float d01 = d0 * d1, d23 = d2 * d3;
            float rp = frcp(d01 * d23);
            float i0 = d1 * d23 * rp;
            float i1 = d0 * d23 * rp;
            float i2 = d3 * d01 * rp;
            float i3 = d2 * d01 * rp;
            T += (i0 + i1) + (i2 + i3);
            S2 = fmaf(i0, i0, fmaf(i1, i1, fmaf(i2, i2, fmaf(i3, i3, S2))));
        }
#pragma unroll
        for (int o = 16; o > 0; o >>= 1) {
            T  += __shfl_xor_sync(0xFFFFFFFFu, T, o);
            S2 += __shfl_xor_sync(0xFFFFFFFFu, S2, o);
        }
        if (lane == 0) { red[par][0][wrp] = T; red[par][1][wrp] = S2; }
        __syncthreads();
        {
            float x = red[par][0][t & 7];
            float y = red[par][1][t & 7];
#pragma unroll
            for (int o = 4; o > 0; o >>= 1) {
                x += __shfl_xor_sync(0xFFFFFFFFu, x, o);
                y += __shfl_xor_sync(0xFFFFFFFFu, y, o);
            }
            T = x; S2 = y;
        }
        float f = T - KF;
        float slope = fmaxf(T - S2, 1e-6f);     // = -dT/dlnw > 0
        float step = f * frcp(slope);           // delta ln w
        step = fminf(4.0f, fmaxf(-4.0f, step));
        w = w * fex2(step * L2E);
        par ^= 1;
        if (fabsf(f) <= 2e-3f) break;           // uniform across block
    }

    // ---- epilogue: P0 = mu/(1+w r) via grouped rcp (no EX2, 1 RCP/quad) ----
    float4* o0 = (float4*)(out + (size_t)b * 2 * NN);
    float4* o1 = (float4*)(out + (size_t)b * 2 * NN + NN);
#pragma unroll
    for (int g = 0; g < NG; g++) {
        float d0 = fmaf(w, r[4 * g + 0], 1.0f);
        float d1 = fmaf(w, r[4 * g + 1], 1.0f);
        float d2 = fmaf(w, r[4 * g + 2], 1.0f);
        float d3 = fmaf(w, r[4 * g + 3], 1.0f);
        float d01 = d0 * d1, d23 = d2 * d3;
        float mrp = MUF * frcp(d01 * d23);
        float4 P0, P1;
        P0.x = d1 * d23 * mrp;
        P0.y = d0 * d23 * mrp;
        P0.z = d3 * d01 * mrp;
        P0.w = d2 * d01 * mrp;
        P1.x = MUF - P0.x;
        P1.y = MUF - P0.y;
        P1.z = MUF - P0.z;
        P1.w = MUF - P0.w;
        o0[g * TPB + t] = P0;
        o1[g * TPB + t] = P1;
    }
}

extern "C" void kernel_launch(void* const* d_in, const int* in_sizes, int n_in,
                              void* d_out, int out_size) {
    const float* scores = (const float*)d_in[0];
    float* out = (float*)d_out;

    max_kernel<<<BATCH, TPB>>>(scores);
    sinkhorn_kernel<<<BATCH, TPB>>>(scores, out);
}